// round 2
// baseline (speedup 1.0000x reference)
#include <cuda_runtime.h>
#include <math.h>

#define HH 36
#define WW 36
#define NPOS (HH*WW)          // 1296
#define CC 64
#define NHEADS 4
#define DHH 16
#define KK 31
#define KK2 (KK*KK)           // 961

// ---------------- scratch (no allocations allowed) ----------------
__device__ float g_qkv [NPOS*192];
__device__ float g_attn[NPOS*CC];
__device__ float g_nat1[NPOS*CC];
__device__ float g_nat2[NPOS*CC];
__device__ float g_tmp [NPOS*CC];

// ---------------- generic GEMM: C(MxN) = A(Mx64) * Wt(Nx64)^T + bias ----------------
__global__ void gemm_bias_kernel(const float* __restrict__ A,
                                 const float* __restrict__ Wt,
                                 const float* __restrict__ bias,
                                 float* __restrict__ Cmat,
                                 int M, int N)
{
    __shared__ float As[32][65];
    __shared__ float Bs[32][65];
    const int tid = threadIdx.x;                  // 256 threads
    const int m0 = blockIdx.y * 32;
    const int n0 = blockIdx.x * 32;

    #pragma unroll
    for (int l = 0; l < 8; l++) {
        int e = tid + l * 256;                    // 0..2047
        int r = e >> 6;
        int c = e & 63;
        int gm = m0 + r;
        As[r][c] = (gm < M) ? A[gm * 64 + c] : 0.f;
        int gn = n0 + r;
        Bs[r][c] = (gn < N) ? Wt[gn * 64 + c] : 0.f;
    }
    __syncthreads();

    const int tx = tid & 31;   // output col within tile
    const int ty = tid >> 5;   // 0..7
    float a0 = 0.f, a1 = 0.f, a2 = 0.f, a3 = 0.f;
    #pragma unroll
    for (int c = 0; c < 64; c++) {
        float b = Bs[tx][c];
        a0 += As[ty     ][c] * b;
        a1 += As[ty +  8][c] * b;
        a2 += As[ty + 16][c] * b;
        a3 += As[ty + 24][c] * b;
    }
    int n = n0 + tx;
    if (n < N) {
        float bv = bias[n];
        int m = m0 + ty;
        if (m      < M) Cmat[(m     ) * N + n] = a0 + bv;
        if (m +  8 < M) Cmat[(m +  8) * N + n] = a1 + bv;
        if (m + 16 < M) Cmat[(m + 16) * N + n] = a2 + bv;
        if (m + 24 < M) Cmat[(m + 24) * N + n] = a3 + bv;
    }
}

// ---------------- NAT2D attention: one query per block ----------------
// qkv: (NPOS, 192) rows = [q(64) | k(64) | v(64)], rpb: (4, 61, 61)
__global__ void nat_attn_kernel(const float* __restrict__ qkv,
                                const float* __restrict__ rpb,
                                float* __restrict__ out)
{
    const int qpos = blockIdx.x;          // 0..1295
    const int qi = qpos / WW;
    const int qj = qpos % WW;
    const int tid  = threadIdx.x;         // 256 threads
    const int lane = tid & 31;
    const int wrp  = tid >> 5;

    __shared__ float s_q[64];
    __shared__ float s_logits[NHEADS][KK2];   // 15376 B
    __shared__ float s_red [8][NHEADS];
    __shared__ float s_red2[8][NHEADS];
    __shared__ float s_part[4][64];

    const int r0 = min(max(qi - (KK/2), 0), HH - KK);   // window row start
    const int c0 = min(max(qj - (KK/2), 0), WW - KK);   // window col start

    if (tid < 64) s_q[tid] = qkv[qpos * 192 + tid];
    __syncthreads();

    // ---- QK + bias -> logits ----
    for (int task = tid; task < KK2 * NHEADS; task += 256) {
        int n  = task >> 2;
        int h  = task & 3;
        int kr = n / KK;
        int kc = n - kr * KK;
        int row = r0 + kr;
        int col = c0 + kc;
        const float4* kv = (const float4*)(qkv + (row * WW + col) * 192 + 64 + h * 16);
        const float4* qv = (const float4*)(s_q + h * 16);
        float4 k0 = kv[0], k1 = kv[1], k2 = kv[2], k3 = kv[3];
        float4 q0 = qv[0], q1 = qv[1], q2 = qv[2], q3 = qv[3];
        float acc = k0.x*q0.x + k0.y*q0.y + k0.z*q0.z + k0.w*q0.w
                  + k1.x*q1.x + k1.y*q1.y + k1.z*q1.z + k1.w*q1.w
                  + k2.x*q2.x + k2.y*q2.y + k2.z*q2.z + k2.w*q2.w
                  + k3.x*q3.x + k3.y*q3.y + k3.z*q3.z + k3.w*q3.w;
        int rrel = row - qi + (KK - 1);
        int crel = col - qj + (KK - 1);
        float bias = rpb[(h * 61 + rrel) * 61 + crel];
        s_logits[h][n] = acc * 0.25f + bias;   // scale = 1/sqrt(16)
    }
    __syncthreads();

    // ---- softmax: max ----
    float m0v = -1e30f, m1v = -1e30f, m2v = -1e30f, m3v = -1e30f;
    for (int n = tid; n < KK2; n += 256) {
        m0v = fmaxf(m0v, s_logits[0][n]);
        m1v = fmaxf(m1v, s_logits[1][n]);
        m2v = fmaxf(m2v, s_logits[2][n]);
        m3v = fmaxf(m3v, s_logits[3][n]);
    }
    #pragma unroll
    for (int off = 16; off; off >>= 1) {
        m0v = fmaxf(m0v, __shfl_xor_sync(0xffffffffu, m0v, off));
        m1v = fmaxf(m1v, __shfl_xor_sync(0xffffffffu, m1v, off));
        m2v = fmaxf(m2v, __shfl_xor_sync(0xffffffffu, m2v, off));
        m3v = fmaxf(m3v, __shfl_xor_sync(0xffffffffu, m3v, off));
    }
    if (lane == 0) { s_red[wrp][0]=m0v; s_red[wrp][1]=m1v; s_red[wrp][2]=m2v; s_red[wrp][3]=m3v; }
    __syncthreads();
    float mx[NHEADS];
    #pragma unroll
    for (int h = 0; h < NHEADS; h++) {
        float m = s_red[0][h];
        #pragma unroll
        for (int w = 1; w < 8; w++) m = fmaxf(m, s_red[w][h]);
        mx[h] = m;
    }

    // ---- softmax: exp + sum (overwrite logits with p) ----
    float s0 = 0.f, s1 = 0.f, s2 = 0.f, s3 = 0.f;
    for (int n = tid; n < KK2; n += 256) {
        float p0 = __expf(s_logits[0][n] - mx[0]); s_logits[0][n] = p0; s0 += p0;
        float p1 = __expf(s_logits[1][n] - mx[1]); s_logits[1][n] = p1; s1 += p1;
        float p2 = __expf(s_logits[2][n] - mx[2]); s_logits[2][n] = p2; s2 += p2;
        float p3 = __expf(s_logits[3][n] - mx[3]); s_logits[3][n] = p3; s3 += p3;
    }
    #pragma unroll
    for (int off = 16; off; off >>= 1) {
        s0 += __shfl_xor_sync(0xffffffffu, s0, off);
        s1 += __shfl_xor_sync(0xffffffffu, s1, off);
        s2 += __shfl_xor_sync(0xffffffffu, s2, off);
        s3 += __shfl_xor_sync(0xffffffffu, s3, off);
    }
    if (lane == 0) { s_red2[wrp][0]=s0; s_red2[wrp][1]=s1; s_red2[wrp][2]=s2; s_red2[wrp][3]=s3; }
    __syncthreads();   // also makes exp'd logits visible to everyone
    float sum[NHEADS];
    #pragma unroll
    for (int h = 0; h < NHEADS; h++) {
        float s = s_red2[0][h];
        #pragma unroll
        for (int w = 1; w < 8; w++) s += s_red2[w][h];
        sum[h] = s;
    }

    // ---- AV: thread (slice, channel) ----
    const int ch    = tid & 63;
    const int slice = tid >> 6;          // 0..3
    const int h2    = ch >> 4;
    float acc = 0.f;
    for (int kr = 0; kr < KK; kr++) {
        const float* vp = qkv + ((r0 + kr) * WW + c0) * 192 + 128 + ch;
        const float* lp = &s_logits[h2][kr * KK];
        for (int kc = slice; kc < KK; kc += 4)
            acc += lp[kc] * vp[kc * 192];
    }
    s_part[slice][ch] = acc;
    __syncthreads();
    if (tid < 64) {
        float tot = s_part[0][tid] + s_part[1][tid] + s_part[2][tid] + s_part[3][tid];
        out[qpos * 64 + tid] = tot / sum[tid >> 4];
    }
}

// ---------------- depthwise 3x3 conv (on original x) + NAT residual add ----------------
__global__ void conv_add_kernel(const float* __restrict__ x,
                                const float* __restrict__ dww,   // (64,1,3,3)
                                const float* __restrict__ dwb,   // (64,)
                                const float* __restrict__ nat2,
                                float* __restrict__ tmp)
{
    int idx = blockIdx.x * blockDim.x + threadIdx.x;
    if (idx >= NPOS * CC) return;
    int c = idx & 63;
    int p = idx >> 6;
    int i = p / WW;
    int j = p % WW;
    float acc = dwb[c];
    #pragma unroll
    for (int dy = 0; dy < 3; dy++) {
        int ii = i + dy - 1;
        if (ii < 0 || ii >= HH) continue;
        #pragma unroll
        for (int dx = 0; dx < 3; dx++) {
            int jj = j + dx - 1;
            if (jj < 0 || jj >= WW) continue;
            acc += x[(ii * WW + jj) * 64 + c] * dww[c * 9 + dy * 3 + dx];
        }
    }
    tmp[idx] = acc + nat2[idx];
}

// ---------------- launcher ----------------
extern "C" void kernel_launch(void* const* d_in, const int* in_sizes, int n_in,
                              void* d_out, int out_size)
{
    const float* x      = (const float*)d_in[0];
    // d_in[1] = H, d_in[2] = W (compile-time constants here)
    const float* qkv_w1 = (const float*)d_in[3];
    const float* qkv_b1 = (const float*)d_in[4];
    const float* rpb1   = (const float*)d_in[5];
    const float* proj_w1= (const float*)d_in[6];
    const float* proj_b1= (const float*)d_in[7];
    const float* qkv_w2 = (const float*)d_in[8];
    const float* qkv_b2 = (const float*)d_in[9];
    const float* rpb2   = (const float*)d_in[10];
    const float* proj_w2= (const float*)d_in[11];
    const float* proj_b2= (const float*)d_in[12];
    const float* dw_w   = (const float*)d_in[13];
    const float* dw_b   = (const float*)d_in[14];
    const float* lin_w  = (const float*)d_in[15];
    const float* lin_b  = (const float*)d_in[16];
    float* out = (float*)d_out;

    float *p_qkv, *p_attn, *p_nat1, *p_nat2, *p_tmp;
    cudaGetSymbolAddress((void**)&p_qkv,  g_qkv);
    cudaGetSymbolAddress((void**)&p_attn, g_attn);
    cudaGetSymbolAddress((void**)&p_nat1, g_nat1);
    cudaGetSymbolAddress((void**)&p_nat2, g_nat2);
    cudaGetSymbolAddress((void**)&p_tmp,  g_tmp);

    dim3 gQKV(6, 41);    // N=192 tiles x M=1296 tiles
    dim3 gN64(2, 41);    // N=64  tiles x M tiles
    const int TB = 256;

    // layer 1
    gemm_bias_kernel<<<gQKV, TB>>>(x, qkv_w1, qkv_b1, p_qkv, NPOS, 192);
    nat_attn_kernel<<<NPOS, TB>>>(p_qkv, rpb1, p_attn);
    gemm_bias_kernel<<<gN64, TB>>>(p_attn, proj_w1, proj_b1, p_nat1, NPOS, 64);
    // layer 2
    gemm_bias_kernel<<<gQKV, TB>>>(p_nat1, qkv_w2, qkv_b2, p_qkv, NPOS, 192);
    nat_attn_kernel<<<NPOS, TB>>>(p_qkv, rpb2, p_attn);
    gemm_bias_kernel<<<gN64, TB>>>(p_attn, proj_w2, proj_b2, p_nat2, NPOS, 64);
    // conv residual + final linear
    conv_add_kernel<<<(NPOS * CC + TB - 1) / TB, TB>>>(x, dw_w, dw_b, p_nat2, p_tmp);
    gemm_bias_kernel<<<gN64, TB>>>(p_tmp, lin_w, lin_b, out, NPOS, 64);
}

// round 3
// speedup vs baseline: 1.1180x; 1.1180x over previous
#include <cuda_runtime.h>
#include <math.h>

#define HH 36
#define WW 36
#define NPOS (HH*WW)          // 1296
#define CC 64
#define KK 31
#define KK2 (KK*KK)           // 961

// ---------------- scratch (no allocations allowed) ----------------
__device__ float g_qkv [NPOS*192];
__device__ float g_attn[NPOS*CC];
__device__ float g_nat1[NPOS*CC];
__device__ float g_nat2[NPOS*CC];
__device__ float g_tmp [NPOS*CC];

// ======================================================================
// GEMM: C(MxN) = A(Mx64) * Wt(Nx64)^T + bias.  64x64 tile, 4x4 per thread.
// ======================================================================
__global__ __launch_bounds__(256) void gemm64_kernel(
    const float* __restrict__ A, const float* __restrict__ Wt,
    const float* __restrict__ bias, float* __restrict__ Cmat, int M, int N)
{
    __shared__ float As[64][65];
    __shared__ float Bs[64][65];
    const int tid = threadIdx.x;
    const int m0 = blockIdx.y * 64;
    const int n0 = blockIdx.x * 64;

    #pragma unroll
    for (int l = 0; l < 16; l++) {
        int e = tid + l * 256;          // 0..4095
        int r = e >> 6, c = e & 63;
        int gm = m0 + r;
        As[r][c] = (gm < M) ? A[gm * 64 + c] : 0.f;
        int gn = n0 + r;
        Bs[r][c] = (gn < N) ? Wt[gn * 64 + c] : 0.f;
    }
    __syncthreads();

    const int tx = tid & 15;
    const int ty = tid >> 4;
    float acc[4][4] = {};
    #pragma unroll
    for (int k = 0; k < 64; k++) {
        float a[4], b[4];
        #pragma unroll
        for (int i = 0; i < 4; i++) { a[i] = As[ty + 16*i][k]; b[i] = Bs[tx + 16*i][k]; }
        #pragma unroll
        for (int i = 0; i < 4; i++)
            #pragma unroll
            for (int j = 0; j < 4; j++)
                acc[i][j] += a[i] * b[j];
    }
    #pragma unroll
    for (int j = 0; j < 4; j++) {
        int n = n0 + tx + 16*j;
        if (n >= N) continue;
        float bv = bias[n];
        #pragma unroll
        for (int i = 0; i < 4; i++) {
            int m = m0 + ty + 16*i;
            if (m < M) Cmat[m * N + n] = acc[i][j] + bv;
        }
    }
}

// ======================================================================
// NAT2D attention, tiled: 8 queries (2 rows x 4 cols) per block, 256 thr.
// qkv rows: [q(64) | k(64) | v(64)].  rpb: (4, 61, 61)
// smem layout (floats):
//   s_q    : 512                        @0
//   s_rsum : 32                         @512
//   s_log  : 32 planes x 968            @544    (plane = q*4+h, n=kr*31+kc)
//   s_KV   : K:[4][34][17] (plane 584)  @31520  (aliased with V:[34][64])
// ======================================================================
#define OFF_RSUM 512
#define OFF_LOG  544
#define OFF_KV   31520
#define SMEM_FLOATS (OFF_KV + 2336)
#define SMEM_BYTES  (SMEM_FLOATS * 4)

__global__ __launch_bounds__(256) void nat_attn_tile(
    const float* __restrict__ qkv, const float* __restrict__ rpb,
    float* __restrict__ out)
{
    extern __shared__ float sm[];
    float* s_q    = sm;
    float* s_rsum = sm + OFF_RSUM;
    float* s_log  = sm + OFF_LOG;
    float* s_KV   = sm + OFF_KV;

    const int tid  = threadIdx.x;
    const int lane = tid & 31;
    const int w    = tid >> 5;
    const int qi0  = blockIdx.y * 2;
    const int qj0  = blockIdx.x * 4;

    // window starts (block-uniform)
    const int r00 = min(max(qi0     - 15, 0), HH - KK);
    const int r01 = min(max(qi0 + 1 - 15, 0), HH - KK);
    int c0arr[4];
    #pragma unroll
    for (int qc = 0; qc < 4; qc++) c0arr[qc] = min(max(qj0 + qc - 15, 0), WW - KK);
    const int c0lo  = c0arr[0];
    const int r0lo  = min(r00, r01);
    const int nrows = max(r00, r01) + KK - r0lo;      // <= 32
    const int ncols = c0arr[3] + KK - c0lo;           // <= 34
    const int nelem = ncols * 64;

    // load q vectors for the 8 queries
    #pragma unroll
    for (int t = tid; t < 512; t += 256) {
        int q = t >> 6, ch = t & 63;
        int pos = (qi0 + (q >> 2)) * WW + qj0 + (q & 3);
        s_q[t] = qkv[pos * 192 + ch];
    }
    __syncthreads();

    // ---------------- pass 1: logits = q.K * scale + bias ----------------
    const int pairq   = w & 3;        // query column; handles queries pairq, pairq+4
    const int colhalf = w >> 2;
    const int h1      = lane >> 3;
    const int slot    = lane & 7;
    float q0r[16], q1r[16];
    #pragma unroll
    for (int i = 0; i < 16; i++) {
        q0r[i] = s_q[pairq * 64 + h1 * 16 + i];
        q1r[i] = s_q[(pairq + 4) * 64 + h1 * 16 + i];
    }
    const int ccb  = c0arr[pairq] - c0lo;
    const int crb  = c0arr[pairq] - (qj0 + pairq) + 30;   // crel base

    float pre[9];
    {   // prefetch K row 0
        const float* src = qkv + (r0lo * WW + c0lo) * 192 + 64;
        #pragma unroll
        for (int l = 0; l < 9; l++) {
            int e = tid + l * 256;
            if (e < nelem) pre[l] = src[(e >> 6) * 192 + (e & 63)];
        }
    }
    for (int rr = 0; rr < nrows; rr++) {
        const int R = r0lo + rr;
        __syncthreads();
        #pragma unroll
        for (int l = 0; l < 9; l++) {           // stage K row (conflict-light)
            int e = tid + l * 256;
            if (e < nelem) {
                int c = e >> 6, ch = e & 63;
                s_KV[(ch >> 4) * 584 + c * 17 + (ch & 15)] = pre[l];
            }
        }
        __syncthreads();
        if (rr + 1 < nrows) {                    // prefetch next K row
            const float* src = qkv + ((R + 1) * WW + c0lo) * 192 + 64;
            #pragma unroll
            for (int l = 0; l < 9; l++) {
                int e = tid + l * 256;
                if (e < nelem) pre[l] = src[(e >> 6) * 192 + (e & 63)];
            }
        }
        const int kr0 = R - r00, kr1 = R - r01;
        const bool v0 = (kr0 >= 0) && (kr0 <= 30);
        const bool v1 = (kr1 >= 0) && (kr1 <= 30);
        const int rrel0 = R - qi0 + 30;
        const float* kbase = s_KV + h1 * 584;
        #pragma unroll
        for (int j = 0; j < 2; j++) {
            int c = slot + 8 * colhalf + 16 * j;
            if (c > 30) continue;
            const float* kp = kbase + (ccb + c) * 17;
            float a0 = 0.f, a1 = 0.f;
            #pragma unroll
            for (int i = 0; i < 16; i++) { float kv = kp[i]; a0 += q0r[i]*kv; a1 += q1r[i]*kv; }
            int crel = crb + c;
            if (v0) s_log[(pairq*4 + h1)*968 + kr0*31 + c] =
                        a0 * 0.25f + __ldg(&rpb[(h1*61 + rrel0)*61 + crel]);
            if (v1) s_log[((pairq+4)*4 + h1)*968 + kr1*31 + c] =
                        a1 * 0.25f + __ldg(&rpb[(h1*61 + rrel0 - 1)*61 + crel]);
        }
    }
    __syncthreads();

    // prefetch V row 0 early (overlaps softmax)
    {
        const float* src = qkv + (r0lo * WW + c0lo) * 192 + 128;
        #pragma unroll
        for (int l = 0; l < 9; l++) {
            int e = tid + l * 256;
            if (e < nelem) pre[l] = src[(e >> 6) * 192 + (e & 63)];
        }
    }

    // ---------------- pass 2: softmax over each (q,h) row of 961 ----------------
    #pragma unroll
    for (int it = 0; it < 4; it++) {
        int idx = w + 8 * it;                 // 0..31 = q*4+h
        float* p = s_log + idx * 968;
        float m = -1e30f;
        for (int n = lane; n < KK2; n += 32) m = fmaxf(m, p[n]);
        #pragma unroll
        for (int off = 16; off; off >>= 1) m = fmaxf(m, __shfl_xor_sync(0xffffffffu, m, off));
        float s = 0.f;
        for (int n = lane; n < KK2; n += 32) { float e = __expf(p[n] - m); p[n] = e; s += e; }
        #pragma unroll
        for (int off = 16; off; off >>= 1) s += __shfl_xor_sync(0xffffffffu, s, off);
        if (lane == 0) s_rsum[idx] = 1.0f / s;
    }
    __syncthreads();

    // ---------------- pass 3: out = P.V ----------------
    const int ch  = tid & 63;
    const int qh  = tid >> 6;       // query column; handles queries qh, qh+4
    const int h3  = ch >> 4;
    const int ccb3 = c0arr[qh] - c0lo;
    float acc0 = 0.f, acc1 = 0.f;

    for (int rr = 0; rr < nrows; rr++) {
        const int R = r0lo + rr;
        __syncthreads();
        #pragma unroll
        for (int l = 0; l < 9; l++) {           // stage V row
            int e = tid + l * 256;
            if (e < nelem) s_KV[(e >> 6) * 64 + (e & 63)] = pre[l];
        }
        __syncthreads();
        if (rr + 1 < nrows) {                    // prefetch next V row
            const float* src = qkv + ((R + 1) * WW + c0lo) * 192 + 128;
            #pragma unroll
            for (int l = 0; l < 9; l++) {
                int e = tid + l * 256;
                if (e < nelem) pre[l] = src[(e >> 6) * 192 + (e & 63)];
            }
        }
        const int kr0 = R - r00, kr1 = R - r01;
        const bool v0 = (kr0 >= 0) && (kr0 <= 30);
        const bool v1 = (kr1 >= 0) && (kr1 <= 30);
        const float* lp0 = s_log + (qh*4 + h3)*968 + kr0*31;
        const float* lp1 = s_log + ((qh+4)*4 + h3)*968 + kr1*31;
        const float* vb  = s_KV + ccb3 * 64 + ch;
        if (v0 && v1) {
            #pragma unroll
            for (int c = 0; c < 31; c++) {
                float vv = vb[c*64];
                acc0 += lp0[c] * vv;
                acc1 += lp1[c] * vv;
            }
        } else if (v0) {
            #pragma unroll
            for (int c = 0; c < 31; c++) acc0 += lp0[c] * vb[c*64];
        } else if (v1) {
            #pragma unroll
            for (int c = 0; c < 31; c++) acc1 += lp1[c] * vb[c*64];
        }
    }

    const float r0s = s_rsum[qh*4 + h3];
    const float r1s = s_rsum[(qh+4)*4 + h3];
    const int pos0 = qi0 * WW + qj0 + qh;
    out[pos0 * 64 + ch]        = acc0 * r0s;
    out[(pos0 + WW) * 64 + ch] = acc1 * r1s;
}

// ---------------- depthwise 3x3 conv (on original x) + NAT residual ----------------
__global__ void conv_add_kernel(const float* __restrict__ x,
                                const float* __restrict__ dww,
                                const float* __restrict__ dwb,
                                const float* __restrict__ nat2,
                                float* __restrict__ tmp)
{
    int idx = blockIdx.x * blockDim.x + threadIdx.x;
    if (idx >= NPOS * CC) return;
    int c = idx & 63;
    int p = idx >> 6;
    int i = p / WW;
    int j = p % WW;
    float acc = dwb[c];
    #pragma unroll
    for (int dy = 0; dy < 3; dy++) {
        int ii = i + dy - 1;
        if (ii < 0 || ii >= HH) continue;
        #pragma unroll
        for (int dx = 0; dx < 3; dx++) {
            int jj = j + dx - 1;
            if (jj < 0 || jj >= WW) continue;
            acc += x[(ii * WW + jj) * 64 + c] * dww[c * 9 + dy * 3 + dx];
        }
    }
    tmp[idx] = acc + nat2[idx];
}

// ---------------- launcher ----------------
extern "C" void kernel_launch(void* const* d_in, const int* in_sizes, int n_in,
                              void* d_out, int out_size)
{
    const float* x      = (const float*)d_in[0];
    const float* qkv_w1 = (const float*)d_in[3];
    const float* qkv_b1 = (const float*)d_in[4];
    const float* rpb1   = (const float*)d_in[5];
    const float* proj_w1= (const float*)d_in[6];
    const float* proj_b1= (const float*)d_in[7];
    const float* qkv_w2 = (const float*)d_in[8];
    const float* qkv_b2 = (const float*)d_in[9];
    const float* rpb2   = (const float*)d_in[10];
    const float* proj_w2= (const float*)d_in[11];
    const float* proj_b2= (const float*)d_in[12];
    const float* dw_w   = (const float*)d_in[13];
    const float* dw_b   = (const float*)d_in[14];
    const float* lin_w  = (const float*)d_in[15];
    const float* lin_b  = (const float*)d_in[16];
    float* out = (float*)d_out;

    float *p_qkv, *p_attn, *p_nat1, *p_nat2, *p_tmp;
    cudaGetSymbolAddress((void**)&p_qkv,  g_qkv);
    cudaGetSymbolAddress((void**)&p_attn, g_attn);
    cudaGetSymbolAddress((void**)&p_nat1, g_nat1);
    cudaGetSymbolAddress((void**)&p_nat2, g_nat2);
    cudaGetSymbolAddress((void**)&p_tmp,  g_tmp);

    cudaFuncSetAttribute(nat_attn_tile,
                         cudaFuncAttributeMaxDynamicSharedMemorySize, SMEM_BYTES);

    dim3 gQKV(3, 21);            // N=192, M=1296 (ceil 64)
    dim3 gN64(1, 21);            // N=64
    dim3 gATT(WW/4, HH/2);       // 9 x 18 = 162 blocks
    const int TB = 256;

    // layer 1
    gemm64_kernel<<<gQKV, TB>>>(x, qkv_w1, qkv_b1, p_qkv, NPOS, 192);
    nat_attn_tile<<<gATT, TB, SMEM_BYTES>>>(p_qkv, rpb1, p_attn);
    gemm64_kernel<<<gN64, TB>>>(p_attn, proj_w1, proj_b1, p_nat1, NPOS, 64);
    // layer 2
    gemm64_kernel<<<gQKV, TB>>>(p_nat1, qkv_w2, qkv_b2, p_qkv, NPOS, 192);
    nat_attn_tile<<<gATT, TB, SMEM_BYTES>>>(p_qkv, rpb2, p_attn);
    gemm64_kernel<<<gN64, TB>>>(p_attn, proj_w2, proj_b2, p_nat2, NPOS, 64);
    // conv residual + final linear
    conv_add_kernel<<<(NPOS * CC + TB - 1) / TB, TB>>>(x, dw_w, dw_b, p_nat2, p_tmp);
    gemm64_kernel<<<gN64, TB>>>(p_tmp, lin_w, lin_b, out, NPOS, 64);
}

// round 4
// speedup vs baseline: 1.9545x; 1.7482x over previous
#include <cuda_runtime.h>
#include <math.h>

#define HH 36
#define WW 36
#define NPOS (HH*WW)          // 1296
#define CC 64
#define KK 31
#define KK2 (KK*KK)           // 961

// ---------------- scratch (no allocations allowed) ----------------
__device__ float g_qkv [NPOS*192];
__device__ float g_attn[NPOS*CC];
__device__ float g_nat1[NPOS*CC];
__device__ float g_nat2[NPOS*CC];
__device__ float g_tmp [NPOS*CC];

// ======================================================================
// GEMM: C(1296xN) = A(1296x64) * Wt(Nx64)^T + bias.  16x64 tile.
// M=1296=81*16 exact, N in {64,192} exact -> no guards.
// ======================================================================
__global__ __launch_bounds__(256) void gemm16_kernel(
    const float* __restrict__ A, const float* __restrict__ Wt,
    const float* __restrict__ bias, float* __restrict__ Cmat, int N)
{
    __shared__ float As[16][68];
    __shared__ float Bs[64][68];
    const int tid = threadIdx.x;
    const int m0 = blockIdx.y * 16;
    const int n0 = blockIdx.x * 64;

    #pragma unroll
    for (int l = 0; l < 4; l++) {
        int e = tid + l * 256;
        As[e >> 6][e & 63] = A[(m0 + (e >> 6)) * 64 + (e & 63)];
    }
    #pragma unroll
    for (int l = 0; l < 16; l++) {
        int e = tid + l * 256;
        Bs[e >> 6][e & 63] = Wt[(n0 + (e >> 6)) * 64 + (e & 63)];
    }
    __syncthreads();

    const int col = tid & 63;
    const int tg  = tid >> 6;           // 0..3 ; rows tg, tg+4, tg+8, tg+12
    float acc[4] = {0.f, 0.f, 0.f, 0.f};
    #pragma unroll
    for (int kb = 0; kb < 16; kb++) {
        float4 b4 = *(const float4*)&Bs[col][kb * 4];
        #pragma unroll
        for (int i = 0; i < 4; i++) {
            float4 a4 = *(const float4*)&As[tg + 4 * i][kb * 4];
            acc[i] += a4.x * b4.x + a4.y * b4.y + a4.z * b4.z + a4.w * b4.w;
        }
    }
    float bv = bias[n0 + col];
    #pragma unroll
    for (int i = 0; i < 4; i++)
        Cmat[(m0 + tg + 4 * i) * N + n0 + col] = acc[i] + bv;
}

// ======================================================================
// NAT2D attention, head-split: block = (2x4 query tile) x 1 head, 256 thr.
// qkv rows: [q(64)|k(64)|v(64)], rpb: (4,61,61)
// smem (floats): s_q[128] @0, s_rsum[8] @128, s_log[8*992] @136,
//                stage[5880] @8072   (K: [8][34] stride20, V: [8][35] stride21)
// ======================================================================
#define OFF_RSUM 128
#define OFF_LOG  136
#define OFF_STG  8072
#define SMEM_FLOATS (OFF_STG + 5880)
#define SMEM_BYTES  (SMEM_FLOATS * 4)

__global__ __launch_bounds__(256) void nat_attn_head(
    const float* __restrict__ qkv, const float* __restrict__ rpb,
    float* __restrict__ out)
{
    extern __shared__ float sm[];
    float* s_q    = sm;
    float* s_rsum = sm + OFF_RSUM;
    float* s_log  = sm + OFF_LOG;
    float* s_stg  = sm + OFF_STG;

    const int tid  = threadIdx.x;
    const int lane = tid & 31;
    const int w    = tid >> 5;          // warp 0..7
    const int qi0  = blockIdx.y * 2;
    const int qj0  = blockIdx.x * 4;
    const int h    = blockIdx.z;

    const int r00 = min(max(qi0     - 15, 0), HH - KK);
    const int r01 = min(max(qi0 + 1 - 15, 0), HH - KK);
    int c0arr[4];
    #pragma unroll
    for (int qc = 0; qc < 4; qc++) c0arr[qc] = min(max(qj0 + qc - 15, 0), WW - KK);
    const int c0lo  = c0arr[0];
    const int r0lo  = min(r00, r01);
    const int nrows = max(r00, r01) + KK - r0lo;      // <= 32

    // stage q (this head's slice) for the 8 queries
    if (tid < 128) {
        int q = tid >> 4, ch = tid & 15;
        int pos = (qi0 + (q >> 2)) * WW + qj0 + (q & 3);
        s_q[tid] = qkv[pos * 192 + h * 16 + ch];
    }
    __syncthreads();

    // ---------------- pass 1: logits ----------------
    const int qc1 = w & 3;              // this warp's query column
    const int rh1 = w >> 2;             // row-half of chunk
    float4 qa[4], qb[4];
    {
        const float4* pa = (const float4*)(s_q + qc1 * 16);
        const float4* pb = (const float4*)(s_q + (4 + qc1) * 16);
        #pragma unroll
        for (int i = 0; i < 4; i++) { qa[i] = pa[i]; qb[i] = pb[i]; }
    }
    const int ccb = c0arr[qc1] - c0lo;
    const int crb = c0arr[qc1] - (qj0 + qc1) + 30;
    const float* rpb_h = rpb + h * 61 * 61;

    for (int chunk = 0; chunk < 4; chunk++) {
        const int base = chunk * 8;
        if (base >= nrows) break;
        __syncthreads();
        // stage K chunk: warp w stages row base+w (34 cols x 16ch, stride 20)
        {
            int rr = base + w;
            if (rr < nrows) {
                const float* src = qkv + (r0lo + rr) * WW * 192 + 64 + h * 16;
                float* dst = s_stg + w * 34 * 20;
                #pragma unroll
                for (int it = 0; it < 17; it++) {
                    int idx = lane + it * 32;        // 0..543
                    int col = idx >> 4, c2 = idx & 15;
                    int gcol = min(c0lo + col, WW - 1);
                    dst[col * 20 + c2] = src[gcol * 192 + c2];
                }
            }
        }
        __syncthreads();
        // compute: rows rh1*4 .. rh1*4+3 of chunk
        #pragma unroll
        for (int rl = 0; rl < 4; rl++) {
            int ric = rh1 * 4 + rl;
            int rr2 = base + ric;
            if (rr2 >= nrows) break;
            int R = r0lo + rr2;
            int kr0 = R - r00, kr1 = R - r01;
            if (lane <= 30) {
                const float4* kp = (const float4*)(s_stg + (ric * 34 + ccb + lane) * 20);
                float4 k0 = kp[0], k1 = kp[1], k2 = kp[2], k3 = kp[3];
                float a0 = qa[0].x*k0.x + qa[0].y*k0.y + qa[0].z*k0.z + qa[0].w*k0.w
                         + qa[1].x*k1.x + qa[1].y*k1.y + qa[1].z*k1.z + qa[1].w*k1.w
                         + qa[2].x*k2.x + qa[2].y*k2.y + qa[2].z*k2.z + qa[2].w*k2.w
                         + qa[3].x*k3.x + qa[3].y*k3.y + qa[3].z*k3.z + qa[3].w*k3.w;
                float a1 = qb[0].x*k0.x + qb[0].y*k0.y + qb[0].z*k0.z + qb[0].w*k0.w
                         + qb[1].x*k1.x + qb[1].y*k1.y + qb[1].z*k1.z + qb[1].w*k1.w
                         + qb[2].x*k2.x + qb[2].y*k2.y + qb[2].z*k2.z + qb[2].w*k2.w
                         + qb[3].x*k3.x + qb[3].y*k3.y + qb[3].z*k3.z + qb[3].w*k3.w;
                int crel  = crb + lane;
                int rrel0 = R - qi0 + 30;
                if (kr0 >= 0 && kr0 <= 30)
                    s_log[qc1 * 992 + kr0 * 32 + lane] =
                        a0 * 0.25f + __ldg(&rpb_h[rrel0 * 61 + crel]);
                if (kr1 >= 0 && kr1 <= 30)
                    s_log[(4 + qc1) * 992 + kr1 * 32 + lane] =
                        a1 * 0.25f + __ldg(&rpb_h[(rrel0 - 1) * 61 + crel]);
            }
        }
    }
    __syncthreads();

    // ---------------- pass 2: softmax (warp w <-> plane w) ----------------
    {
        float* p = s_log + w * 992;
        float m = -1e30f;
        for (int n = lane; n < 992; n += 32) {
            float x = ((n & 31) < 31) ? p[n] : -1e30f;
            m = fmaxf(m, x);
        }
        #pragma unroll
        for (int off = 16; off; off >>= 1)
            m = fmaxf(m, __shfl_xor_sync(0xffffffffu, m, off));
        float s = 0.f;
        for (int n = lane; n < 992; n += 32) {
            float x = ((n & 31) < 31) ? p[n] : -1e30f;
            float e = __expf(x - m);
            p[n] = e;                    // c==31 slots become exactly 0
            s += e;
        }
        #pragma unroll
        for (int off = 16; off; off >>= 1)
            s += __shfl_xor_sync(0xffffffffu, s, off);
        if (lane == 0) s_rsum[w] = 1.0f / s;
    }

    // ---------------- pass 3: out = P.V ----------------
    const int q3   = tid >> 5;          // warp id == query id
    const int half = (tid >> 4) & 1;
    const int ch   = tid & 15;
    const int qc3  = q3 & 3, qr3 = q3 >> 2;
    const int r0q  = qr3 ? r01 : r00;
    const int ccbq = c0arr[qc3] - c0lo;
    float acc = 0.f;

    for (int chunk = 0; chunk < 4; chunk++) {
        const int base = chunk * 8;
        if (base >= nrows) break;
        __syncthreads();
        // stage V chunk: warp q3 stages row base+q3 (35 cols x 16ch, stride 21)
        {
            int rr = base + q3;
            if (rr < nrows) {
                const float* src = qkv + (r0lo + rr) * WW * 192 + 128 + h * 16;
                float* dst = s_stg + q3 * 35 * 21;
                #pragma unroll
                for (int it = 0; it < 18; it++) {
                    int idx = lane + it * 32;        // 0..575, use <560
                    if (idx < 560) {
                        int col = idx >> 4, c2 = idx & 15;
                        int gcol = min(c0lo + col, WW - 1);
                        dst[col * 21 + c2] = src[gcol * 192 + c2];
                    }
                }
            }
        }
        __syncthreads();
        const int rend = min(8, nrows - base);
        for (int ric = 0; ric < rend; ric++) {
            int R  = r0lo + base + ric;
            int kr = R - r0q;
            if (kr < 0 || kr > 30) continue;
            const float* lp = s_log + q3 * 992 + kr * 32 + half * 16;
            const float* vp = s_stg + (ric * 35 + ccbq + half * 16) * 21 + ch;
            #pragma unroll
            for (int jb = 0; jb < 4; jb++) {
                float4 l4 = *(const float4*)(lp + jb * 4);
                acc += l4.x * vp[(jb * 4 + 0) * 21];
                acc += l4.y * vp[(jb * 4 + 1) * 21];
                acc += l4.z * vp[(jb * 4 + 2) * 21];
                acc += l4.w * vp[(jb * 4 + 3) * 21];
            }
        }
    }
    acc += __shfl_xor_sync(0xffffffffu, acc, 16);
    if (half == 0) {
        int pos = (qi0 + qr3) * WW + qj0 + qc3;
        out[pos * 64 + h * 16 + ch] = acc * s_rsum[q3];
    }
}

// ---------------- depthwise 3x3 conv (on original x) + NAT residual ----------------
__global__ void conv_add_kernel(const float* __restrict__ x,
                                const float* __restrict__ dww,
                                const float* __restrict__ dwb,
                                const float* __restrict__ nat2,
                                float* __restrict__ tmp)
{
    int idx = blockIdx.x * blockDim.x + threadIdx.x;
    if (idx >= NPOS * CC) return;
    int c = idx & 63;
    int p = idx >> 6;
    int i = p / WW;
    int j = p % WW;
    float acc = dwb[c];
    #pragma unroll
    for (int dy = 0; dy < 3; dy++) {
        int ii = i + dy - 1;
        if (ii < 0 || ii >= HH) continue;
        #pragma unroll
        for (int dx = 0; dx < 3; dx++) {
            int jj = j + dx - 1;
            if (jj < 0 || jj >= WW) continue;
            acc += x[(ii * WW + jj) * 64 + c] * dww[c * 9 + dy * 3 + dx];
        }
    }
    tmp[idx] = acc + nat2[idx];
}

// ---------------- launcher ----------------
extern "C" void kernel_launch(void* const* d_in, const int* in_sizes, int n_in,
                              void* d_out, int out_size)
{
    const float* x      = (const float*)d_in[0];
    const float* qkv_w1 = (const float*)d_in[3];
    const float* qkv_b1 = (const float*)d_in[4];
    const float* rpb1   = (const float*)d_in[5];
    const float* proj_w1= (const float*)d_in[6];
    const float* proj_b1= (const float*)d_in[7];
    const float* qkv_w2 = (const float*)d_in[8];
    const float* qkv_b2 = (const float*)d_in[9];
    const float* rpb2   = (const float*)d_in[10];
    const float* proj_w2= (const float*)d_in[11];
    const float* proj_b2= (const float*)d_in[12];
    const float* dw_w   = (const float*)d_in[13];
    const float* dw_b   = (const float*)d_in[14];
    const float* lin_w  = (const float*)d_in[15];
    const float* lin_b  = (const float*)d_in[16];
    float* out = (float*)d_out;

    float *p_qkv, *p_attn, *p_nat1, *p_nat2, *p_tmp;
    cudaGetSymbolAddress((void**)&p_qkv,  g_qkv);
    cudaGetSymbolAddress((void**)&p_attn, g_attn);
    cudaGetSymbolAddress((void**)&p_nat1, g_nat1);
    cudaGetSymbolAddress((void**)&p_nat2, g_nat2);
    cudaGetSymbolAddress((void**)&p_tmp,  g_tmp);

    cudaFuncSetAttribute(nat_attn_head,
                         cudaFuncAttributeMaxDynamicSharedMemorySize, SMEM_BYTES);

    dim3 gQKV(3, 81);                 // N=192
    dim3 gN64(1, 81);                 // N=64
    dim3 gATT(WW/4, HH/2, 4);         // 9 x 18 x 4 heads = 648 blocks
    const int TB = 256;

    // layer 1
    gemm16_kernel<<<gQKV, TB>>>(x, qkv_w1, qkv_b1, p_qkv, 192);
    nat_attn_head<<<gATT, TB, SMEM_BYTES>>>(p_qkv, rpb1, p_attn);
    gemm16_kernel<<<gN64, TB>>>(p_attn, proj_w1, proj_b1, p_nat1, 64);
    // layer 2
    gemm16_kernel<<<gQKV, TB>>>(p_nat1, qkv_w2, qkv_b2, p_qkv, 192);
    nat_attn_head<<<gATT, TB, SMEM_BYTES>>>(p_qkv, rpb2, p_attn);
    gemm16_kernel<<<gN64, TB>>>(p_attn, proj_w2, proj_b2, p_nat2, 64);
    // conv residual + final linear
    conv_add_kernel<<<(NPOS * CC + TB - 1) / TB, TB>>>(x, dw_w, dw_b, p_nat2, p_tmp);
    gemm16_kernel<<<gN64, TB>>>(p_tmp, lin_w, lin_b, out, 64);
}